// round 16
// baseline (speedup 1.0000x reference)
#include <cuda_runtime.h>
#include <math.h>

#define Bc 4
#define Cc 128
#define Dc 64
#define Nc 2048
#define Mc 2048
#define Hc 256
#define Kc 16
#define NPTS (Bc*Nc*Kc)   // 131072
#define EPSf 1e-5f

typedef unsigned long long u64;

__device__ __forceinline__ u64 pack2(float lo, float hi) {
    u64 r; asm("mov.b64 %0, {%1,%2};" : "=l"(r) : "f"(lo), "f"(hi)); return r;
}
__device__ __forceinline__ float2 unpack2(u64 v) {
    float2 r; asm("mov.b64 {%0,%1}, %2;" : "=f"(r.x), "=f"(r.y) : "l"(v)); return r;
}
__device__ __forceinline__ u64 fma2(u64 a, u64 b, u64 c) {
    u64 d; asm("fma.rn.f32x2 %0, %1, %2, %3;" : "=l"(d) : "l"(a), "l"(b), "l"(c)); return d;
}

// ---------------- scratch -----------------------------------------------
__device__ __align__(256) float g_q[Bc*Nc*Dc];
__device__ __align__(256) float g_k[Bc*Mc*Dc];
__device__ __align__(256) float g_v[Bc*Mc*Dc];
__device__ __align__(256) int   g_idx[NPTS];
__device__ __align__(256) float g_pe[NPTS*Dc];
__device__ __align__(256) float g_s[NPTS*Dc];             // S tiles [tile][e][pt]
__device__ __align__(256) float g_a1[(size_t)NPTS*Hc];    // [h][pt]
__device__ __align__(256) float g_agg[Bc*Nc*Dc];
__device__ double g_sum1[Dc], g_sq1[Dc];
__device__ double g_sum2[Hc], g_sq2[Hc];
// transposed weights (written by qkv's prep blocks; consumed by later launches)
__device__ __align__(256) float g_Wp2t[Dc*Dc];  // [e][d]
__device__ __align__(256) float g_Wa1t[Dc*Hc];  // [e][h]
__device__ __align__(256) float g_Wa2t[Hc*Dc];  // [h][d]
__device__ __align__(256) float g_Wet[Dc*Cc];   // [d][c]

// ---------------- q/k/v convs (+ embedded weight-prep blocks) ---------------
__global__ __launch_bounds__(512, 2)
void qkv_kernel(const float* __restrict__ fq, const float* __restrict__ fs,
                const float* __restrict__ Wq, const float* __restrict__ bq,
                const float* __restrict__ Wk, const float* __restrict__ bk,
                const float* __restrict__ Wv, const float* __restrict__ bv,
                const float* __restrict__ Wp2, const float* __restrict__ Wa1,
                const float* __restrict__ Wa2, const float* __restrict__ We) {
    int zw = blockIdx.y;
    int t = threadIdx.x;
    if (zw >= 12) {
        int g0 = blockIdx.x*512 + t;
        if (zw == 12) {
            for (int i = g0; i < Dc*Hc; i += 16*512) { int e = i/Hc, h = i%Hc; g_Wa1t[i] = Wa1[h*Dc + e]; }
        } else {
            for (int i = g0; i < Dc*Dc; i += 16*512) { int e = i/Dc, d = i%Dc; g_Wp2t[i] = Wp2[d*Dc + e]; }
            for (int i = g0; i < Hc*Dc; i += 16*512) { int h = i/Dc, d = i%Dc; g_Wa2t[i] = Wa2[d*Hc + h]; }
            for (int i = g0; i < Dc*Cc; i += 16*512) { int d = i/Cc, c = i%Cc; g_Wet[i]  = We[c*Dc + d]; }
        }
        return;
    }
    extern __shared__ float sm0[];
    float* sWt = sm0;           // [128 c][64 d] transposed in-kernel
    float* sF = sWt + Cc*Dc;    // [32 c][128 n]
    float* sb = sF + 32*128;    // 64
    int which = zw >> 2, b = zw & 3;
    const float* f    = (which == 0) ? fq : fs;
    const float* W    = (which == 0) ? Wq : (which == 1 ? Wk : Wv);
    const float* bias = (which == 0) ? bq : (which == 1 ? bk : bv);
    float* out        = (which == 0) ? g_q : (which == 1 ? g_k : g_v);
    for (int i = t; i < Dc*Cc; i += 512) {
        int d = i >> 7, c = i & 127;
        sWt[c*Dc + d] = W[i];
    }
    if (t < Dc) sb[t] = bias[t];
    int nblk = blockIdx.x * 128;
    const float* fb = f + (size_t)b*Cc*Nc + nblk;
    int og = t >> 5, pg = t & 31;
    int d0 = og*4, n0 = pg*4;
    u64 acc[4][2];
    #pragma unroll
    for (int q = 0; q < 4; q++) { acc[q][0] = 0ull; acc[q][1] = 0ull; }
    for (int ks = 0; ks < 4; ks++) {
        int c0 = ks*32;
        __syncthreads();
        for (int i = t; i < 1024; i += 512) {
            int cl = i >> 5, nl4 = (i & 31);
            ((float4*)sF)[cl*32 + nl4] = *(const float4*)&fb[(size_t)(c0 + cl)*Nc + nl4*4];
        }
        __syncthreads();
        #pragma unroll 4
        for (int cl = 0; cl < 32; cl++) {
            ulonglong2 x2 = *(const ulonglong2*)&sF[cl*128 + n0];
            float4 w4 = *(const float4*)&sWt[(c0+cl)*Dc + d0];
            u64 w0 = pack2(w4.x, w4.x), w1 = pack2(w4.y, w4.y);
            u64 w2 = pack2(w4.z, w4.z), w3 = pack2(w4.w, w4.w);
            acc[0][0] = fma2(w0, x2.x, acc[0][0]); acc[0][1] = fma2(w0, x2.y, acc[0][1]);
            acc[1][0] = fma2(w1, x2.x, acc[1][0]); acc[1][1] = fma2(w1, x2.y, acc[1][1]);
            acc[2][0] = fma2(w2, x2.x, acc[2][0]); acc[2][1] = fma2(w2, x2.y, acc[2][1]);
            acc[3][0] = fma2(w3, x2.x, acc[3][0]); acc[3][1] = fma2(w3, x2.y, acc[3][1]);
        }
    }
    float b0 = sb[d0], b1 = sb[d0+1], b2 = sb[d0+2], b3 = sb[d0+3];
    float vx[4][4];
    #pragma unroll
    for (int q = 0; q < 4; q++) {
        float2 lo = unpack2(acc[q][0]), hi = unpack2(acc[q][1]);
        vx[q][0]=lo.x; vx[q][1]=lo.y; vx[q][2]=hi.x; vx[q][3]=hi.y;
    }
    #pragma unroll
    for (int j = 0; j < 4; j++) {
        int n = nblk + n0 + j;
        float4 o = make_float4(vx[0][j]+b0, vx[1][j]+b1, vx[2][j]+b2, vx[3][j]+b3);
        *(float4*)&out[((size_t)b*Nc + n)*Dc + d0] = o;
    }
}

// ---------------- KNN -------------------------------------------------------
__global__ __launch_bounds__(256, 2)
void knn_kernel(const float* __restrict__ pq, const float* __restrict__ ps) {
    extern __shared__ float smk[];
    float4* sp = (float4*)smk;
    float*  cd = smk + 2048*4;
    int*    ci = (int*)(cd + 64*65);
    int t = threadIdx.x;
    int b = blockIdx.y;
    if (blockIdx.x == 0 && blockIdx.y == 0) {
        if (t < Dc) { g_sum1[t] = 0.0; g_sq1[t] = 0.0; }
        g_sum2[t] = 0.0; g_sq2[t] = 0.0;
    }
    const float* p = ps + (size_t)b*3*Mc;
    for (int i = t; i < Mc; i += 256) {
        float x = p[i], y = p[Mc + i], z = p[2*Mc + i];
        sp[i] = make_float4(x, y, z, x*x + y*y + z*z);
    }
    __syncthreads();
    int qi = t & 63, chunk = t >> 6;
    int n = blockIdx.x * 64 + qi;
    const float* pqb = pq + (size_t)b*3*Nc;
    float qx = pqb[n], qy = pqb[Nc + n], qz = pqb[2*Nc + n];
    float qq = qx*qx + qy*qy + qz*qz;
    float bd[Kc]; int bi[Kc];
    #pragma unroll
    for (int j = 0; j < Kc; j++) { bd[j] = 3.4e38f; bi[j] = 0; }
    float worst = 3.4e38f; int wpos = 0;
    int m0 = chunk*512;
    #pragma unroll 2
    for (int mm = 0; mm < 512; mm++) {
        int m = m0 + mm;
        float4 c = sp[m];
        float dot = qx*c.x + qy*c.y + qz*c.z;
        float d2 = qq + c.w - 2.0f*dot;
        if (d2 < worst) {
            #pragma unroll
            for (int j = 0; j < Kc; j++) if (j == wpos) { bd[j] = d2; bi[j] = m; }
            worst = -3.4e38f;
            #pragma unroll
            for (int j = 0; j < Kc; j++) if (bd[j] > worst) { worst = bd[j]; wpos = j; }
        }
    }
    #pragma unroll
    for (int j = 0; j < Kc; j++) {
        cd[qi*65 + chunk*16 + j] = bd[j];
        ci[qi*65 + chunk*16 + j] = bi[j];
    }
    __syncthreads();
    if (t < 64) {
        float fd[Kc]; int fi[Kc];
        #pragma unroll
        for (int j = 0; j < Kc; j++) { fd[j] = 3.4e38f; fi[j] = 0; }
        float w2 = 3.4e38f; int wp2 = 0;
        for (int c = 0; c < 64; c++) {
            float d2 = cd[t*65 + c];
            int   iv = ci[t*65 + c];
            if (d2 < w2) {
                #pragma unroll
                for (int j = 0; j < Kc; j++) if (j == wp2) { fd[j] = d2; fi[j] = iv; }
                w2 = -3.4e38f;
                #pragma unroll
                for (int j = 0; j < Kc; j++) if (fd[j] > w2) { w2 = fd[j]; wp2 = j; }
            }
        }
        int nn = blockIdx.x * 64 + t;
        int* o = g_idx + ((size_t)b*Nc + nn)*Kc;
        #pragma unroll
        for (int j = 0; j < Kc; j++) o[j] = fi[j];
    }
}

// ---------------- pe1 = Wp1 @ pos_rel + bp1, fused BN1 stats ---------------
__global__ __launch_bounds__(256, 4)
void pe1_stats_kernel(const float* __restrict__ pq, const float* __restrict__ ps,
                      const float* __restrict__ Wp1, const float* __restrict__ bp1) {
    __shared__ float srel[256*3];
    __shared__ float ssum[4*64], ssq[4*64];
    int p0 = blockIdx.x * 256;
    int t = threadIdx.x;
    {
        int p = p0 + t;
        int b = p >> 15;
        int nq = (p & 32767) >> 4;
        int iv = g_idx[p];
        const float* pqb = pq + (size_t)b*3*Nc;
        const float* psb = ps + (size_t)b*3*Mc;
        srel[t*3+0] = pqb[nq]        - psb[iv];
        srel[t*3+1] = pqb[Nc + nq]   - psb[Mc + iv];
        srel[t*3+2] = pqb[2*Nc + nq] - psb[2*Mc + iv];
    }
    __syncthreads();
    int d = t & 63, slot = t >> 6;
    float w0 = Wp1[d*3], w1 = Wp1[d*3+1], w2 = Wp1[d*3+2], bb = bp1[d];
    float s = 0.f, s2 = 0.f;
    int i0 = slot*64;
    for (int i = i0; i < i0+64; i++) {
        float x = fmaf(w0, srel[i*3], fmaf(w1, srel[i*3+1], fmaf(w2, srel[i*3+2], bb)));
        g_pe[(size_t)(p0 + i)*Dc + d] = x;
        s += x; s2 += x*x;
    }
    ssum[slot*64 + d] = s;
    ssq[slot*64 + d] = s2;
    __syncthreads();
    if (t < 64) {
        float ts = ssum[t] + ssum[64+t] + ssum[128+t] + ssum[192+t];
        float tq = ssq[t]  + ssq[64+t]  + ssq[128+t]  + ssq[192+t];
        atomicAdd(&g_sum1[t], (double)ts);
        atomicAdd(&g_sq1[t],  (double)tq);
    }
}

// ---------------- pe2_s: pe = Wp2 @ relu(BN1(pe1)) + bp2 ; S = pe + q - k ---
__global__ __launch_bounds__(256, 3)
void pe2_s_kernel(const float* __restrict__ bp2,
                  const float* __restrict__ gp, const float* __restrict__ btp) {
    extern __shared__ float sm5[];
    float* sW   = sm5;            // [64 e][64 d] Wp2t
    float* sX   = sW + 4096;      // [64 e][128 pt]
    float* sbn  = sX + 8192;      // 64
    float* ssh  = sbn + Dc;       // 64
    float* sbp2 = ssh + Dc;       // 64
    int t = threadIdx.x;
    for (int i = t; i < 1024; i += 256) ((float4*)sW)[i] = ((const float4*)g_Wp2t)[i];
    if (t < Dc) {
        const double inv = 1.0 / (double)NPTS;
        double m = g_sum1[t]*inv;
        double v = g_sq1[t]*inv - m*m;
        float rs = rsqrtf((float)v + EPSf);
        float sc = gp[t] * rs;
        sbn[t] = sc;
        ssh[t] = btp[t] - (float)m*sc;
        sbp2[t] = bp2[t];
    }
    int p0 = blockIdx.x * 128;
    __syncthreads();
    for (int f = t; f < 2048; f += 256) {
        int d4 = f >> 7, ptl = f & 127;
        float4 v = *(const float4*)&g_pe[(size_t)(p0 + ptl)*Dc + d4*4];
        int d = d4*4;
        sX[(d+0)*128 + ptl] = fmaxf(fmaf(v.x, sbn[d+0], ssh[d+0]), 0.f);
        sX[(d+1)*128 + ptl] = fmaxf(fmaf(v.y, sbn[d+1], ssh[d+1]), 0.f);
        sX[(d+2)*128 + ptl] = fmaxf(fmaf(v.z, sbn[d+2], ssh[d+2]), 0.f);
        sX[(d+3)*128 + ptl] = fmaxf(fmaf(v.w, sbn[d+3], ssh[d+3]), 0.f);
    }
    __syncthreads();
    // GEMM: 8d x 4pt per thread
    int og = t >> 5, pg = t & 31;
    int d0 = og*8, pt0 = pg*4;
    u64 acc[8][2];
    #pragma unroll
    for (int q = 0; q < 8; q++) { acc[q][0] = 0ull; acc[q][1] = 0ull; }
    #pragma unroll 4
    for (int e = 0; e < Dc; e++) {
        ulonglong2 x2 = *(const ulonglong2*)&sX[e*128 + pt0];
        float4 wa = *(const float4*)&sW[e*Dc + d0];
        float4 wb = *(const float4*)&sW[e*Dc + d0 + 4];
        float wf[8] = {wa.x, wa.y, wa.z, wa.w, wb.x, wb.y, wb.z, wb.w};
        #pragma unroll
        for (int q = 0; q < 8; q++) {
            u64 wp = pack2(wf[q], wf[q]);
            acc[q][0] = fma2(wp, x2.x, acc[q][0]);
            acc[q][1] = fma2(wp, x2.y, acc[q][1]);
        }
    }
    float vx[8][4];
    #pragma unroll
    for (int q = 0; q < 8; q++) {
        float2 lo = unpack2(acc[q][0]), hi = unpack2(acc[q][1]);
        float bb = sbp2[d0+q];
        vx[q][0] = lo.x + bb; vx[q][1] = lo.y + bb;
        vx[q][2] = hi.x + bb; vx[q][3] = hi.y + bb;
    }
    float sv[8][4];
    #pragma unroll
    for (int j = 0; j < 4; j++) {
        int pt = p0 + pt0 + j;
        int b  = pt >> 15;
        int nq = (pt & 32767) >> 4;
        int iv = g_idx[pt];
        float4 qa = *(const float4*)&g_q[((size_t)b*Nc + nq)*Dc + d0];
        float4 qb = *(const float4*)&g_q[((size_t)b*Nc + nq)*Dc + d0 + 4];
        float4 ka = *(const float4*)&g_k[((size_t)b*Mc + iv)*Dc + d0];
        float4 kb = *(const float4*)&g_k[((size_t)b*Mc + iv)*Dc + d0 + 4];
        float4 pa = make_float4(vx[0][j], vx[1][j], vx[2][j], vx[3][j]);
        float4 pb = make_float4(vx[4][j], vx[5][j], vx[6][j], vx[7][j]);
        *(float4*)&g_pe[(size_t)pt*Dc + d0]     = pa;
        *(float4*)&g_pe[(size_t)pt*Dc + d0 + 4] = pb;
        sv[0][j] = pa.x + qa.x - ka.x; sv[1][j] = pa.y + qa.y - ka.y;
        sv[2][j] = pa.z + qa.z - ka.z; sv[3][j] = pa.w + qa.w - ka.w;
        sv[4][j] = pb.x + qb.x - kb.x; sv[5][j] = pb.y + qb.y - kb.y;
        sv[6][j] = pb.z + qb.z - kb.z; sv[7][j] = pb.w + qb.w - kb.w;
    }
    float* so = g_s + (size_t)blockIdx.x*8192;
    #pragma unroll
    for (int r = 0; r < 8; r++)
        *(float4*)&so[(d0+r)*128 + pt0] = make_float4(sv[r][0], sv[r][1], sv[r][2], sv[r][3]);
}

// ---------------- a1 = Wa1 @ S + ba1 (pure GEMM) + BN2 stats ---------------
// Block: 64 h x 128 pt; grid (NPTS/128, 4). Thread: 8h x 8pt; warp 64h x 32pt.
__global__ __launch_bounds__(128, 3)
void a1_kernel(const float* __restrict__ ba1) {
    extern __shared__ float sm9[];
    float* sWh = sm9;           // [64 e][64 h]
    float* sS  = sWh + 4096;    // [64 e][128 pt]
    float* sba = sS + 8192;     // 64
    int t = threadIdx.x;
    int lane = t & 31, w = t >> 5;
    int p0 = blockIdx.x * 128;
    int hbase = blockIdx.y * 64;
    for (int i = t; i < 1024; i += 128) {
        int e = i >> 4, hl4 = i & 15;
        ((float4*)&sWh[e*64])[hl4] = *(const float4*)&g_Wa1t[e*Hc + hbase + hl4*4];
    }
    {
        const float4* src = (const float4*)(g_s + (size_t)blockIdx.x*8192);
        for (int i = t; i < 2048; i += 128) ((float4*)sS)[i] = src[i];
    }
    if (t < 64) sba[t] = ba1[hbase + t];
    __syncthreads();
    // 2-D warp tile: h0l from lane>>2, pt0 from (w, lane&3)
    int h0l = (lane >> 2)*8;                 // 0..56
    int pt0 = (w*4 + (lane & 3))*8;          // 0..120
    u64 a[8][4];
    #pragma unroll
    for (int hh = 0; hh < 8; hh++)
        #pragma unroll
        for (int j = 0; j < 4; j++) a[hh][j] = 0ull;
    for (int e = 0; e < Dc; e++) {
        ulonglong2 xa = *(const ulonglong2*)&sS[e*128 + pt0];
        ulonglong2 xb = *(const ulonglong2*)&sS[e*128 + pt0 + 4];
        float4 wa = *(const float4*)&sWh[e*64 + h0l];
        float4 wb = *(const float4*)&sWh[e*64 + h0l + 4];
        float wf[8] = {wa.x, wa.y, wa.z, wa.w, wb.x, wb.y, wb.z, wb.w};
        #pragma unroll
        for (int hh = 0; hh < 8; hh++) {
            u64 wp = pack2(wf[hh], wf[hh]);
            a[hh][0] = fma2(wp, xa.x, a[hh][0]);
            a[hh][1] = fma2(wp, xa.y, a[hh][1]);
            a[hh][2] = fma2(wp, xb.x, a[hh][2]);
            a[hh][3] = fma2(wp, xb.y, a[hh][3]);
        }
    }
    #pragma unroll
    for (int hh = 0; hh < 8; hh++) {
        int h = hbase + h0l + hh;
        float bias = sba[h0l + hh];
        float vv[8];
        #pragma unroll
        for (int j = 0; j < 4; j++) {
            float2 u = unpack2(a[hh][j]);
            vv[j*2+0] = u.x + bias;
            vv[j*2+1] = u.y + bias;
        }
        float s = 0.f, s2 = 0.f;
        #pragma unroll
        for (int j = 0; j < 8; j++) { s += vv[j]; s2 += vv[j]*vv[j]; }
        float* op = &g_a1[(size_t)h*NPTS + p0 + pt0];
        *(float4*)op       = make_float4(vv[0], vv[1], vv[2], vv[3]);
        *(float4*)(op + 4) = make_float4(vv[4], vv[5], vv[6], vv[7]);
        // reduce over 4-lane pt group within warp; both warps emit atomics
        s  += __shfl_xor_sync(0xffffffffu, s, 1);
        s2 += __shfl_xor_sync(0xffffffffu, s2, 1);
        s  += __shfl_xor_sync(0xffffffffu, s, 2);
        s2 += __shfl_xor_sync(0xffffffffu, s2, 2);
        if ((lane & 3) == 0) {
            atomicAdd(&g_sum2[h], (double)s);
            atomicAdd(&g_sq2[h],  (double)s2);
        }
    }
}

// ---------------- a2 = Wa2 @ relu(BN2(a1)) + ba2 ; softmax; aggregate ------
// 128 threads; thread 8d x 8pt; warp 64d x 32pt; 4 h-chunks of 64.
__global__ __launch_bounds__(128, 4)
void a2_softagg_kernel(const float* __restrict__ ba2,
                       const float* __restrict__ ga,  const float* __restrict__ bta) {
    extern __shared__ float sm7[];
    float* sW   = sm7;             // [64 hl][64 d] chunk ; sOut overlays sm7
    float* sA   = sW + 64*Dc;      // [64 hl][128 pt]
    float* ssc  = sA + 64*128;     // 256
    float* ssh2 = ssc + Hc;        // 256
    float* sba2 = ssh2 + Hc;       // 64
    int t = threadIdx.x;
    int lane = t & 31, w = t >> 5;
    int p0 = blockIdx.x * 128;
    int b  = p0 >> 15;
    for (int i = t; i < Hc; i += 128) {
        const double inv = 1.0 / (double)NPTS;
        double m = g_sum2[i]*inv;
        double v = g_sq2[i]*inv - m*m;
        float rs = rsqrtf((float)v + EPSf);
        float sc = ga[i] * rs;
        ssc[i] = sc;
        ssh2[i] = bta[i] - (float)m*sc;
    }
    if (t < Dc) sba2[t] = ba2[t];
    // 2-D warp tile: d0 from lane>>2, pt0 from (w, lane&3)
    int d0 = (lane >> 2)*8;                  // 0..56
    int pt0 = (w*4 + (lane & 3))*8;          // 0..120
    u64 acc[8][4];
    #pragma unroll
    for (int q = 0; q < 8; q++)
        #pragma unroll
        for (int j = 0; j < 4; j++) acc[q][j] = 0ull;
    for (int ks = 0; ks < 4; ks++) {
        int h0k = ks*64;
        __syncthreads();
        for (int i = t; i < 1024; i += 128)
            ((float4*)sW)[i] = ((const float4*)(g_Wa2t + (size_t)h0k*Dc))[i];
        for (int f = t; f < 2048; f += 128) {
            int hl = f >> 5, pt4 = f & 31;
            int h = h0k + hl;
            float4 v = *(const float4*)&g_a1[(size_t)h*NPTS + p0 + pt4*4];
            float sc = ssc[h], sh = ssh2[h];
            float4 o = make_float4(fmaxf(fmaf(v.x, sc, sh), 0.f),
                                   fmaxf(fmaf(v.y, sc, sh), 0.f),
                                   fmaxf(fmaf(v.z, sc, sh), 0.f),
                                   fmaxf(fmaf(v.w, sc, sh), 0.f));
            *(float4*)&sA[hl*128 + pt4*4] = o;
        }
        __syncthreads();
        for (int hl = 0; hl < 64; hl++) {
            ulonglong2 xa = *(const ulonglong2*)&sA[hl*128 + pt0];
            ulonglong2 xb = *(const ulonglong2*)&sA[hl*128 + pt0 + 4];
            float4 wa = *(const float4*)&sW[hl*Dc + d0];
            float4 wb = *(const float4*)&sW[hl*Dc + d0 + 4];
            float wf[8] = {wa.x, wa.y, wa.z, wa.w, wb.x, wb.y, wb.z, wb.w};
            #pragma unroll
            for (int q = 0; q < 8; q++) {
                u64 wp = pack2(wf[q], wf[q]);
                acc[q][0] = fma2(wp, xa.x, acc[q][0]);
                acc[q][1] = fma2(wp, xa.y, acc[q][1]);
                acc[q][2] = fma2(wp, xb.x, acc[q][2]);
                acc[q][3] = fma2(wp, xb.y, acc[q][3]);
            }
        }
    }
    __syncthreads();
    float* sOut = sm7;    // [128 pt][65]
    #pragma unroll
    for (int q = 0; q < 8; q++) {
        float bb = sba2[d0+q];
        float vv[8];
        #pragma unroll
        for (int j = 0; j < 4; j++) {
            float2 u = unpack2(acc[q][j]);
            vv[j*2+0] = u.x + bb; vv[j*2+1] = u.y + bb;
        }
        #pragma unroll
        for (int p = 0; p < 8; p++)
            sOut[(pt0+p)*65 + d0+q] = vv[p];
    }
    __syncthreads();
    int d  = t & 63;
    for (int nl = (t >> 6); nl < 8; nl += 2) {
        int base = nl*16;
        float av[Kc];
        float mx = -3.4e38f;
        #pragma unroll
        for (int k = 0; k < Kc; k++) {
            av[k] = sOut[(base + k)*65 + d];
            mx = fmaxf(mx, av[k]);
        }
        float sum = 0.f;
        #pragma unroll
        for (int k = 0; k < Kc; k++) { av[k] = __expf(av[k] - mx); sum += av[k]; }
        float inv = 1.f / sum;
        const int* ip = g_idx + p0 + base;
        float agg = 0.f;
        #pragma unroll
        for (int k = 0; k < Kc; k++) {
            int iv = ip[k];
            float vg = g_v[((size_t)b*Mc + iv)*Dc + d];
            float pe = g_pe[(size_t)(p0 + base + k)*Dc + d];
            agg = fmaf(av[k]*inv, vg + pe, agg);
        }
        int bn = (p0 >> 4) + nl;
        g_agg[(size_t)bn*Dc + d] = agg;
    }
}

// ---------------- out = We @ agg + be + fq ---------------------------------
__global__ __launch_bounds__(512, 2)
void final_kernel(const float* __restrict__ be,
                  const float* __restrict__ fq, float* __restrict__ out) {
    extern __shared__ float sm8[];
    float* sWet = sm8;             // [64 d][128 c]
    float* sG  = sWet + Dc*Cc;     // [64 d][128 n]
    float* sbe = sG + Dc*128;      // 128
    int t = threadIdx.x;
    int b = blockIdx.y;
    int nblk = blockIdx.x * 128;
    for (int i = t; i < Cc*Dc/4; i += 512) ((float4*)sWet)[i] = ((const float4*)g_Wet)[i];
    if (t < Cc) sbe[t] = be[t];
    for (int f = t; f < 2048; f += 512) {
        int d4 = f >> 7, nl = f & 127;
        float4 v = *(const float4*)&g_agg[((size_t)b*Nc + nblk + nl)*Dc + d4*4];
        int d = d4*4;
        sG[(d+0)*128 + nl] = v.x;
        sG[(d+1)*128 + nl] = v.y;
        sG[(d+2)*128 + nl] = v.z;
        sG[(d+3)*128 + nl] = v.w;
    }
    __syncthreads();
    int og = t >> 4, pg = t & 15;
    int c0 = og*4, n0 = pg*8;
    u64 acc[4][4];
    #pragma unroll
    for (int q = 0; q < 4; q++)
        #pragma unroll
        for (int j = 0; j < 4; j++) acc[q][j] = 0ull;
    #pragma unroll 2
    for (int e = 0; e < Dc; e++) {
        ulonglong2 xa = *(const ulonglong2*)&sG[e*128 + n0];
        ulonglong2 xb = *(const ulonglong2*)&sG[e*128 + n0 + 4];
        float4 w4 = *(const float4*)&sWet[e*Cc + c0];
        float wf[4] = {w4.x, w4.y, w4.z, w4.w};
        #pragma unroll
        for (int q = 0; q < 4; q++) {
            u64 wp = pack2(wf[q], wf[q]);
            acc[q][0] = fma2(wp, xa.x, acc[q][0]);
            acc[q][1] = fma2(wp, xa.y, acc[q][1]);
            acc[q][2] = fma2(wp, xb.x, acc[q][2]);
            acc[q][3] = fma2(wp, xb.y, acc[q][3]);
        }
    }
    #pragma unroll
    for (int q = 0; q < 4; q++) {
        int c = c0 + q;
        float bc = sbe[c];
        float vv[8];
        #pragma unroll
        for (int j = 0; j < 4; j++) {
            float2 u = unpack2(acc[q][j]);
            vv[j*2+0] = u.x; vv[j*2+1] = u.y;
        }
        size_t o = (size_t)b*Cc*Nc + (size_t)c*Nc + nblk + n0;
        float4 f0 = *(const float4*)&fq[o];
        float4 f1 = *(const float4*)&fq[o + 4];
        *(float4*)&out[o]     = make_float4(vv[0]+bc+f0.x, vv[1]+bc+f0.y,
                                            vv[2]+bc+f0.z, vv[3]+bc+f0.w);
        *(float4*)&out[o + 4] = make_float4(vv[4]+bc+f1.x, vv[5]+bc+f1.y,
                                            vv[6]+bc+f1.z, vv[7]+bc+f1.w);
    }
}

// ---------------- launch -----------------------------------------------------
extern "C" void kernel_launch(void* const* d_in, const int* in_sizes, int n_in,
                              void* d_out, int out_size) {
    const float* pq  = (const float*)d_in[0];
    const float* fq  = (const float*)d_in[1];
    const float* ps  = (const float*)d_in[2];
    const float* fs  = (const float*)d_in[3];
    const float* Wq  = (const float*)d_in[4];  const float* bq  = (const float*)d_in[5];
    const float* Wk  = (const float*)d_in[6];  const float* bk  = (const float*)d_in[7];
    const float* Wv  = (const float*)d_in[8];  const float* bv  = (const float*)d_in[9];
    const float* Wp1 = (const float*)d_in[10]; const float* bp1 = (const float*)d_in[11];
    const float* gp  = (const float*)d_in[12]; const float* btp = (const float*)d_in[13];
    const float* Wp2 = (const float*)d_in[14]; const float* bp2 = (const float*)d_in[15];
    const float* Wa1 = (const float*)d_in[16]; const float* ba1 = (const float*)d_in[17];
    const float* ga  = (const float*)d_in[18]; const float* bta = (const float*)d_in[19];
    const float* Wa2 = (const float*)d_in[20]; const float* ba2 = (const float*)d_in[21];
    const float* We  = (const float*)d_in[22]; const float* be  = (const float*)d_in[23];
    float* out = (float*)d_out;

    const int SMEM_QKV = (Cc*Dc + 32*128 + Dc) * (int)sizeof(float);
    const int SMEM_KNN = 2048*16 + 64*65*4*2;
    const int SMEM_PS  = (4096 + 8192 + 3*Dc) * (int)sizeof(float);
    const int SMEM_A1  = (4096 + 8192 + Dc) * (int)sizeof(float);
    const int SMEM_A2  = (64*Dc + 8320 + 2*Hc + Dc) * (int)sizeof(float);
    const int SMEM_FIN = (Dc*Cc + Dc*128 + Cc) * (int)sizeof(float);
    cudaFuncSetAttribute(qkv_kernel,        cudaFuncAttributeMaxDynamicSharedMemorySize, SMEM_QKV);
    cudaFuncSetAttribute(knn_kernel,        cudaFuncAttributeMaxDynamicSharedMemorySize, SMEM_KNN);
    cudaFuncSetAttribute(pe2_s_kernel,      cudaFuncAttributeMaxDynamicSharedMemorySize, SMEM_PS);
    cudaFuncSetAttribute(a1_kernel,         cudaFuncAttributeMaxDynamicSharedMemorySize, SMEM_A1);
    cudaFuncSetAttribute(a2_softagg_kernel, cudaFuncAttributeMaxDynamicSharedMemorySize, SMEM_A2);
    cudaFuncSetAttribute(final_kernel,      cudaFuncAttributeMaxDynamicSharedMemorySize, SMEM_FIN);

    qkv_kernel<<<dim3(Nc/128, 14), 512, SMEM_QKV>>>(fq, fs, Wq, bq, Wk, bk, Wv, bv,
                                                    Wp2, Wa1, Wa2, We);
    knn_kernel<<<dim3(Nc/64, Bc), 256, SMEM_KNN>>>(pq, ps);
    pe1_stats_kernel<<<NPTS/256, 256>>>(pq, ps, Wp1, bp1);
    pe2_s_kernel<<<NPTS/128, 256, SMEM_PS>>>(bp2, gp, btp);
    a1_kernel<<<dim3(NPTS/128, 4), 128, SMEM_A1>>>(ba1);
    a2_softagg_kernel<<<NPTS/128, 128, SMEM_A2>>>(ba2, ga, bta);
    final_kernel<<<dim3(Nc/128, Bc), 512, SMEM_FIN>>>(be, fq, out);
}

// round 17
// speedup vs baseline: 1.3388x; 1.3388x over previous
#include <cuda_runtime.h>
#include <math.h>

#define Bc 4
#define Cc 128
#define Dc 64
#define Nc 2048
#define Mc 2048
#define Hc 256
#define Kc 16
#define NPTS (Bc*Nc*Kc)   // 131072
#define EPSf 1e-5f

typedef unsigned long long u64;

__device__ __forceinline__ u64 pack2(float lo, float hi) {
    u64 r; asm("mov.b64 %0, {%1,%2};" : "=l"(r) : "f"(lo), "f"(hi)); return r;
}
__device__ __forceinline__ float2 unpack2(u64 v) {
    float2 r; asm("mov.b64 {%0,%1}, %2;" : "=f"(r.x), "=f"(r.y) : "l"(v)); return r;
}
__device__ __forceinline__ u64 fma2(u64 a, u64 b, u64 c) {
    u64 d; asm("fma.rn.f32x2 %0, %1, %2, %3;" : "=l"(d) : "l"(a), "l"(b), "l"(c)); return d;
}

// ---------------- scratch -----------------------------------------------
__device__ __align__(256) float g_q[Bc*Nc*Dc];
__device__ __align__(256) float g_k[Bc*Mc*Dc];
__device__ __align__(256) float g_v[Bc*Mc*Dc];
__device__ __align__(256) int   g_idx[NPTS];
__device__ __align__(256) float g_pe[NPTS*Dc];
__device__ __align__(256) float g_a1[(size_t)NPTS*Hc];    // [h][pt]
__device__ __align__(256) float g_agg[Bc*Nc*Dc];
__device__ double g_sum1[Dc], g_sq1[Dc];
__device__ double g_sum2[Hc], g_sq2[Hc];
// transposed weights
__device__ __align__(256) float g_Wqt[Cc*Dc];   // [c][d]
__device__ __align__(256) float g_Wkt[Cc*Dc];
__device__ __align__(256) float g_Wvt[Cc*Dc];
__device__ __align__(256) float g_Wp2t[Dc*Dc];  // [e][d]
__device__ __align__(256) float g_Wa1t[Dc*Hc];  // [e][h]
__device__ __align__(256) float g_Wa2t[Hc*Dc];  // [h][d]
__device__ __align__(256) float g_Wet[Dc*Cc];   // [d][c]

// ---------------- prep: transpose weights ----------------------------------
__global__ void prep_kernel(const float* __restrict__ Wq, const float* __restrict__ Wk,
                            const float* __restrict__ Wv, const float* __restrict__ Wp2,
                            const float* __restrict__ Wa1, const float* __restrict__ Wa2,
                            const float* __restrict__ We) {
    int job = blockIdx.y;
    int i0 = blockIdx.x * 256 + threadIdx.x;
    int stride = gridDim.x * 256;
    if (job == 0) { for (int i = i0; i < Cc*Dc; i += stride) { int c = i/Dc, d = i%Dc; g_Wqt[i]  = Wq[d*Cc + c]; } }
    else if (job == 1) { for (int i = i0; i < Cc*Dc; i += stride) { int c = i/Dc, d = i%Dc; g_Wkt[i]  = Wk[d*Cc + c]; } }
    else if (job == 2) { for (int i = i0; i < Cc*Dc; i += stride) { int c = i/Dc, d = i%Dc; g_Wvt[i]  = Wv[d*Cc + c]; } }
    else if (job == 3) { for (int i = i0; i < Dc*Dc; i += stride) { int e = i/Dc, d = i%Dc; g_Wp2t[i] = Wp2[d*Dc + e]; } }
    else if (job == 4) { for (int i = i0; i < Dc*Hc; i += stride) { int e = i/Hc, h = i%Hc; g_Wa1t[i] = Wa1[h*Dc + e]; } }
    else if (job == 5) { for (int i = i0; i < Hc*Dc; i += stride) { int h = i/Dc, d = i%Dc; g_Wa2t[i] = Wa2[d*Hc + h]; } }
    else               { for (int i = i0; i < Dc*Cc; i += stride) { int d = i/Cc, c = i%Cc; g_Wet[i]  = We[c*Dc + d]; } }
}

// ---------------- q/k/v 1x1 convs as tiled GEMM ----------------------------
__global__ __launch_bounds__(512, 2)
void qkv_kernel(const float* __restrict__ fq, const float* __restrict__ fs,
                const float* __restrict__ bq, const float* __restrict__ bk,
                const float* __restrict__ bv) {
    extern __shared__ float sm0[];
    float* sWt = sm0;           // [128 c][64 d] transposed
    float* sF = sWt + Cc*Dc;    // [32 c][128 n]
    float* sb = sF + 32*128;    // 64
    int zw = blockIdx.y;
    int which = zw >> 2, b = zw & 3;
    const float* f    = (which == 0) ? fq : fs;
    const float* Wt   = (which == 0) ? g_Wqt : (which == 1 ? g_Wkt : g_Wvt);
    const float* bias = (which == 0) ? bq : (which == 1 ? bk : bv);
    float* out        = (which == 0) ? g_q : (which == 1 ? g_k : g_v);
    int t = threadIdx.x;
    for (int i = t; i < Cc*Dc/4; i += 512) ((float4*)sWt)[i] = ((const float4*)Wt)[i];
    if (t < Dc) sb[t] = bias[t];
    int nblk = blockIdx.x * 128;
    const float* fb = f + (size_t)b*Cc*Nc + nblk;
    int og = t >> 5, pg = t & 31;
    int d0 = og*4, n0 = pg*4;
    u64 acc[4][2];
    #pragma unroll
    for (int q = 0; q < 4; q++) { acc[q][0] = 0ull; acc[q][1] = 0ull; }
    for (int ks = 0; ks < 4; ks++) {
        int c0 = ks*32;
        __syncthreads();
        for (int i = t; i < 1024; i += 512) {
            int cl = i >> 5, nl4 = (i & 31);
            ((float4*)sF)[cl*32 + nl4] = *(const float4*)&fb[(size_t)(c0 + cl)*Nc + nl4*4];
        }
        __syncthreads();
        #pragma unroll 4
        for (int cl = 0; cl < 32; cl++) {
            ulonglong2 x2 = *(const ulonglong2*)&sF[cl*128 + n0];
            float4 w4 = *(const float4*)&sWt[(c0+cl)*Dc + d0];
            u64 w0 = pack2(w4.x, w4.x), w1 = pack2(w4.y, w4.y);
            u64 w2 = pack2(w4.z, w4.z), w3 = pack2(w4.w, w4.w);
            acc[0][0] = fma2(w0, x2.x, acc[0][0]); acc[0][1] = fma2(w0, x2.y, acc[0][1]);
            acc[1][0] = fma2(w1, x2.x, acc[1][0]); acc[1][1] = fma2(w1, x2.y, acc[1][1]);
            acc[2][0] = fma2(w2, x2.x, acc[2][0]); acc[2][1] = fma2(w2, x2.y, acc[2][1]);
            acc[3][0] = fma2(w3, x2.x, acc[3][0]); acc[3][1] = fma2(w3, x2.y, acc[3][1]);
        }
    }
    float b0 = sb[d0], b1 = sb[d0+1], b2 = sb[d0+2], b3 = sb[d0+3];
    float vx[4][4];
    #pragma unroll
    for (int q = 0; q < 4; q++) {
        float2 lo = unpack2(acc[q][0]), hi = unpack2(acc[q][1]);
        vx[q][0]=lo.x; vx[q][1]=lo.y; vx[q][2]=hi.x; vx[q][3]=hi.y;
    }
    #pragma unroll
    for (int j = 0; j < 4; j++) {
        int n = nblk + n0 + j;
        float4 o = make_float4(vx[0][j]+b0, vx[1][j]+b1, vx[2][j]+b2, vx[3][j]+b3);
        *(float4*)&out[((size_t)b*Nc + n)*Dc + d0] = o;
    }
}

// ---------------- KNN: 4 threads/query, chunked scan + merge ---------------
__global__ __launch_bounds__(256, 2)
void knn_kernel(const float* __restrict__ pq, const float* __restrict__ ps) {
    extern __shared__ float smk[];
    float4* sp = (float4*)smk;          // 2048 float4 = 32 KB
    float*  cd = smk + 2048*4;
    int*    ci = (int*)(cd + 64*65);
    int t = threadIdx.x;
    int b = blockIdx.y;
    if (blockIdx.x == 0 && blockIdx.y == 0) {
        if (t < Dc) { g_sum1[t] = 0.0; g_sq1[t] = 0.0; }
        g_sum2[t] = 0.0; g_sq2[t] = 0.0;
    }
    const float* p = ps + (size_t)b*3*Mc;
    for (int i = t; i < Mc; i += 256) {
        float x = p[i], y = p[Mc + i], z = p[2*Mc + i];
        sp[i] = make_float4(x, y, z, x*x + y*y + z*z);
    }
    __syncthreads();
    int qi = t & 63, chunk = t >> 6;
    int n = blockIdx.x * 64 + qi;
    const float* pqb = pq + (size_t)b*3*Nc;
    float qx = pqb[n], qy = pqb[Nc + n], qz = pqb[2*Nc + n];
    float qq = qx*qx + qy*qy + qz*qz;
    float bd[Kc]; int bi[Kc];
    #pragma unroll
    for (int j = 0; j < Kc; j++) { bd[j] = 3.4e38f; bi[j] = 0; }
    float worst = 3.4e38f; int wpos = 0;
    int m0 = chunk*512;
    #pragma unroll 2
    for (int mm = 0; mm < 512; mm++) {
        int m = m0 + mm;
        float4 c = sp[m];
        float dot = qx*c.x + qy*c.y + qz*c.z;
        float d2 = qq + c.w - 2.0f*dot;
        if (d2 < worst) {
            #pragma unroll
            for (int j = 0; j < Kc; j++) if (j == wpos) { bd[j] = d2; bi[j] = m; }
            worst = -3.4e38f;
            #pragma unroll
            for (int j = 0; j < Kc; j++) if (bd[j] > worst) { worst = bd[j]; wpos = j; }
        }
    }
    #pragma unroll
    for (int j = 0; j < Kc; j++) {
        cd[qi*65 + chunk*16 + j] = bd[j];
        ci[qi*65 + chunk*16 + j] = bi[j];
    }
    __syncthreads();
    if (t < 64) {
        float fd[Kc]; int fi[Kc];
        #pragma unroll
        for (int j = 0; j < Kc; j++) { fd[j] = 3.4e38f; fi[j] = 0; }
        float w2 = 3.4e38f; int wp2 = 0;
        for (int c = 0; c < 64; c++) {
            float d2 = cd[t*65 + c];
            int   iv = ci[t*65 + c];
            if (d2 < w2) {
                #pragma unroll
                for (int j = 0; j < Kc; j++) if (j == wp2) { fd[j] = d2; fi[j] = iv; }
                w2 = -3.4e38f;
                #pragma unroll
                for (int j = 0; j < Kc; j++) if (fd[j] > w2) { w2 = fd[j]; wp2 = j; }
            }
        }
        int nn = blockIdx.x * 64 + t;
        int* o = g_idx + ((size_t)b*Nc + nn)*Kc;
        #pragma unroll
        for (int j = 0; j < Kc; j++) o[j] = fi[j];
    }
}

// ---------------- pe1 = Wp1 @ pos_rel + bp1, fused BN1 stats ---------------
__global__ __launch_bounds__(256, 4)
void pe1_stats_kernel(const float* __restrict__ pq, const float* __restrict__ ps,
                      const float* __restrict__ Wp1, const float* __restrict__ bp1) {
    __shared__ float srel[256*3];
    __shared__ float ssum[4*64], ssq[4*64];
    int p0 = blockIdx.x * 256;
    int t = threadIdx.x;
    {
        int p = p0 + t;
        int b = p >> 15;
        int nq = (p & 32767) >> 4;
        int iv = g_idx[p];
        const float* pqb = pq + (size_t)b*3*Nc;
        const float* psb = ps + (size_t)b*3*Mc;
        srel[t*3+0] = pqb[nq]        - psb[iv];
        srel[t*3+1] = pqb[Nc + nq]   - psb[Mc + iv];
        srel[t*3+2] = pqb[2*Nc + nq] - psb[2*Mc + iv];
    }
    __syncthreads();
    int d = t & 63, slot = t >> 6;
    float w0 = Wp1[d*3], w1 = Wp1[d*3+1], w2 = Wp1[d*3+2], bb = bp1[d];
    float s = 0.f, s2 = 0.f;
    int i0 = slot*64;
    for (int i = i0; i < i0+64; i++) {
        float x = fmaf(w0, srel[i*3], fmaf(w1, srel[i*3+1], fmaf(w2, srel[i*3+2], bb)));
        g_pe[(size_t)(p0 + i)*Dc + d] = x;
        s += x; s2 += x*x;
    }
    ssum[slot*64 + d] = s;
    ssq[slot*64 + d] = s2;
    __syncthreads();
    if (t < 64) {
        float ts = ssum[t] + ssum[64+t] + ssum[128+t] + ssum[192+t];
        float tq = ssq[t]  + ssq[64+t]  + ssq[128+t]  + ssq[192+t];
        atomicAdd(&g_sum1[t], (double)ts);
        atomicAdd(&g_sq1[t],  (double)tq);
    }
}

// ---------------- pe = Wp2 @ relu(BN1(pe1)) + bp2 ; a1 = Wa1 @ (q-k+pe) + ba1
// Best-measured config: occ 1, single-pass 8h x 8pt stage2, sW time-multiplexed.
__global__ __launch_bounds__(512, 1)
void pe2_a1_kernel(const float* __restrict__ bp2,
                   const float* __restrict__ gp,  const float* __restrict__ btp,
                   const float* __restrict__ ba1) {
    extern __shared__ float sm6[];
    float* sW   = sm6;                 // 16384 floats: Wp2t [e][d], then Wa1t [e][h]
    float* sX   = sW + 16384;          // [64 e][128 pt]
    float* sbn  = sX + Dc*128;         // 64
    float* ssh  = sbn + Dc;            // 64
    float* sbp2 = ssh + Dc;            // 64
    float* sba1 = sbp2 + Dc;           // 256
    int t = threadIdx.x;
    for (int i = t; i < 1024; i += 512) ((float4*)sW)[i] = ((const float4*)g_Wp2t)[i];
    for (int i = t; i < 3072; i += 512) ((float4*)(sW + 4096))[i] = ((const float4*)(g_Wa1t + 4096))[i];
    if (t < Dc) {
        const double inv = 1.0 / (double)NPTS;
        double m = g_sum1[t]*inv;
        double v = g_sq1[t]*inv - m*m;
        float rs = rsqrtf((float)v + EPSf);
        float sc = gp[t] * rs;
        sbn[t] = sc;
        ssh[t] = btp[t] - (float)m*sc;
        sbp2[t] = bp2[t];
    }
    if (t < Hc) sba1[t] = ba1[t];
    int p0 = blockIdx.x * 128;
    __syncthreads();
    // load pe1 tile transposed, apply BN1+relu
    for (int f = t; f < 2048; f += 512) {
        int d4 = f >> 7, ptl = f & 127;
        float4 v = *(const float4*)&g_pe[(size_t)(p0 + ptl)*Dc + d4*4];
        int d = d4*4;
        sX[(d+0)*128 + ptl] = fmaxf(fmaf(v.x, sbn[d+0], ssh[d+0]), 0.f);
        sX[(d+1)*128 + ptl] = fmaxf(fmaf(v.y, sbn[d+1], ssh[d+1]), 0.f);
        sX[(d+2)*128 + ptl] = fmaxf(fmaf(v.z, sbn[d+2], ssh[d+2]), 0.f);
        sX[(d+3)*128 + ptl] = fmaxf(fmaf(v.w, sbn[d+3], ssh[d+3]), 0.f);
    }
    __syncthreads();
    // -------- Stage 1 GEMM: pe = Wp2 @ Xr (4d x 4pt) --------
    int og2 = t >> 5, pg2 = t & 31;
    int d0 = og2*4, pt0s = pg2*4;
    u64 acc1[4][2];
    #pragma unroll
    for (int q = 0; q < 4; q++) { acc1[q][0] = 0ull; acc1[q][1] = 0ull; }
    #pragma unroll 4
    for (int e = 0; e < Dc; e++) {
        ulonglong2 x2 = *(const ulonglong2*)&sX[e*128 + pt0s];
        float4 w4 = *(const float4*)&sW[e*Dc + d0];
        u64 w0 = pack2(w4.x, w4.x), w1 = pack2(w4.y, w4.y);
        u64 w2 = pack2(w4.z, w4.z), w3 = pack2(w4.w, w4.w);
        acc1[0][0] = fma2(w0, x2.x, acc1[0][0]); acc1[0][1] = fma2(w0, x2.y, acc1[0][1]);
        acc1[1][0] = fma2(w1, x2.x, acc1[1][0]); acc1[1][1] = fma2(w1, x2.y, acc1[1][1]);
        acc1[2][0] = fma2(w2, x2.x, acc1[2][0]); acc1[2][1] = fma2(w2, x2.y, acc1[2][1]);
        acc1[3][0] = fma2(w3, x2.x, acc1[3][0]); acc1[3][1] = fma2(w3, x2.y, acc1[3][1]);
    }
    __syncthreads();   // stage1 reads of sW + sX done
    // epilogue 1: write pe; S = pe + q - k into sX; load Wa1t rows e<16
    {
        float vx[4][4];
        #pragma unroll
        for (int q = 0; q < 4; q++) {
            float2 lo = unpack2(acc1[q][0]), hi = unpack2(acc1[q][1]);
            float bb = sbp2[d0+q];
            vx[q][0] = lo.x + bb; vx[q][1] = lo.y + bb;
            vx[q][2] = hi.x + bb; vx[q][3] = hi.y + bb;
        }
        #pragma unroll
        for (int j = 0; j < 4; j++) {
            int pt = p0 + pt0s + j;
            int b  = pt >> 15;
            int nq = (pt & 32767) >> 4;
            int iv = g_idx[pt];
            float4 q4 = *(const float4*)&g_q[((size_t)b*Nc + nq)*Dc + d0];
            float4 k4 = *(const float4*)&g_k[((size_t)b*Mc + iv)*Dc + d0];
            float4 pe4 = make_float4(vx[0][j], vx[1][j], vx[2][j], vx[3][j]);
            *(float4*)&g_pe[(size_t)pt*Dc + d0] = pe4;
            sX[(d0+0)*128 + pt0s + j] = pe4.x + q4.x - k4.x;
            sX[(d0+1)*128 + pt0s + j] = pe4.y + q4.y - k4.y;
            sX[(d0+2)*128 + pt0s + j] = pe4.z + q4.z - k4.z;
            sX[(d0+3)*128 + pt0s + j] = pe4.w + q4.w - k4.w;
        }
    }
    for (int i = t; i < 1024; i += 512) ((float4*)sW)[i] = ((const float4*)g_Wa1t)[i];
    __syncthreads();
    // -------- Stage 2 GEMM: a1 = Wa1 @ S, 8h x 8pt, single pass ------------
    int og = t >> 4, pg = t & 15;
    int h0 = og*8, pt0 = pg*8;
    u64 a[8][4];
    #pragma unroll
    for (int hh = 0; hh < 8; hh++)
        #pragma unroll
        for (int j = 0; j < 4; j++) a[hh][j] = 0ull;
    for (int e = 0; e < Dc; e++) {
        ulonglong2 xa = *(const ulonglong2*)&sX[e*128 + pt0];
        ulonglong2 xb = *(const ulonglong2*)&sX[e*128 + pt0 + 4];
        float4 wa = *(const float4*)&sW[e*Hc + h0];
        float4 wb = *(const float4*)&sW[e*Hc + h0 + 4];
        float wf[8] = {wa.x, wa.y, wa.z, wa.w, wb.x, wb.y, wb.z, wb.w};
        #pragma unroll
        for (int hh = 0; hh < 8; hh++) {
            u64 wp = pack2(wf[hh], wf[hh]);
            a[hh][0] = fma2(wp, xa.x, a[hh][0]);
            a[hh][1] = fma2(wp, xa.y, a[hh][1]);
            a[hh][2] = fma2(wp, xb.x, a[hh][2]);
            a[hh][3] = fma2(wp, xb.y, a[hh][3]);
        }
    }
    // epilogue 2: bias, store g_a1[h][pt], BN2 stats
    #pragma unroll
    for (int hh = 0; hh < 8; hh++) {
        int h = h0 + hh;
        float bias = sba1[h];
        float vv[8];
        #pragma unroll
        for (int j = 0; j < 4; j++) {
            float2 u = unpack2(a[hh][j]);
            vv[j*2+0] = u.x + bias;
            vv[j*2+1] = u.y + bias;
        }
        float s = 0.f, s2 = 0.f;
        #pragma unroll
        for (int j = 0; j < 8; j++) { s += vv[j]; s2 += vv[j]*vv[j]; }
        float* op = &g_a1[(size_t)h*NPTS + p0 + pt0];
        *(float4*)op       = make_float4(vv[0], vv[1], vv[2], vv[3]);
        *(float4*)(op + 4) = make_float4(vv[4], vv[5], vv[6], vv[7]);
        #pragma unroll
        for (int off = 8; off > 0; off >>= 1) {
            s  += __shfl_xor_sync(0xffffffffu, s, off);
            s2 += __shfl_xor_sync(0xffffffffu, s2, off);
        }
        if (pg == 0) {
            atomicAdd(&g_sum2[h], (double)s);
            atomicAdd(&g_sq2[h],  (double)s2);
        }
    }
}

// ---------------- a2 = Wa2 @ relu(BN2(a1)) + ba2 ; softmax; aggregate ------
// 128 threads, 8d x 8pt tiles, 4 chunks of 64 h.
__global__ __launch_bounds__(128, 4)
void a2_softagg_kernel(const float* __restrict__ ba2,
                       const float* __restrict__ ga,  const float* __restrict__ bta) {
    extern __shared__ float sm7[];
    float* sW   = sm7;             // [64 hl][64 d] chunk ; sOut overlays sm7
    float* sA   = sW + 64*Dc;      // [64 hl][128 pt]
    float* ssc  = sA + 64*128;     // 256
    float* ssh2 = ssc + Hc;        // 256
    float* sba2 = ssh2 + Hc;       // 64
    int t = threadIdx.x;
    int p0 = blockIdx.x * 128;
    int b  = p0 >> 15;
    for (int i = t; i < Hc; i += 128) {
        const double inv = 1.0 / (double)NPTS;
        double m = g_sum2[i]*inv;
        double v = g_sq2[i]*inv - m*m;
        float rs = rsqrtf((float)v + EPSf);
        float sc = ga[i] * rs;
        ssc[i] = sc;
        ssh2[i] = bta[i] - (float)m*sc;
    }
    if (t < Dc) sba2[t] = ba2[t];
    int og = t >> 4, pg = t & 15;
    int d0 = og*8, pt0 = pg*8;
    u64 acc[8][4];
    #pragma unroll
    for (int q = 0; q < 8; q++)
        #pragma unroll
        for (int j = 0; j < 4; j++) acc[q][j] = 0ull;
    for (int ks = 0; ks < 4; ks++) {
        int h0k = ks*64;
        __syncthreads();
        for (int i = t; i < 1024; i += 128)
            ((float4*)sW)[i] = ((const float4*)(g_Wa2t + (size_t)h0k*Dc))[i];
        for (int f = t; f < 2048; f += 128) {
            int hl = f >> 5, pt4 = f & 31;
            int h = h0k + hl;
            float4 v = *(const float4*)&g_a1[(size_t)h*NPTS + p0 + pt4*4];
            float sc = ssc[h], sh = ssh2[h];
            float4 o = make_float4(fmaxf(fmaf(v.x, sc, sh), 0.f),
                                   fmaxf(fmaf(v.y, sc, sh), 0.f),
                                   fmaxf(fmaf(v.z, sc, sh), 0.f),
                                   fmaxf(fmaf(v.w, sc, sh), 0.f));
            *(float4*)&sA[hl*128 + pt4*4] = o;
        }
        __syncthreads();
        for (int hl = 0; hl < 64; hl++) {
            ulonglong2 xa = *(const ulonglong2*)&sA[hl*128 + pt0];
            ulonglong2 xb = *(const ulonglong2*)&sA[hl*128 + pt0 + 4];
            float4 wa = *(const float4*)&sW[hl*Dc + d0];
            float4 wb = *(const float4*)&sW[hl*Dc + d0 + 4];
            float wf[8] = {wa.x, wa.y, wa.z, wa.w, wb.x, wb.y, wb.z, wb.w};
            #pragma unroll
            for (int q = 0; q < 8; q++) {
                u64 wp = pack2(wf[q], wf[q]);
                acc[q][0] = fma2(wp, xa.x, acc[q][0]);
                acc[q][1] = fma2(wp, xa.y, acc[q][1]);
                acc[q][2] = fma2(wp, xb.x, acc[q][2]);
                acc[q][3] = fma2(wp, xb.y, acc[q][3]);
            }
        }
    }
    __syncthreads();
    float* sOut = sm7;    // [128 pt][65]
    #pragma unroll
    for (int q = 0; q < 8; q++) {
        float bb = sba2[d0+q];
        float vv[8];
        #pragma unroll
        for (int j = 0; j < 4; j++) {
            float2 u = unpack2(acc[q][j]);
            vv[j*2+0] = u.x + bb; vv[j*2+1] = u.y + bb;
        }
        #pragma unroll
        for (int p = 0; p < 8; p++)
            sOut[(pt0+p)*65 + d0+q] = vv[p];
    }
    __syncthreads();
    int d  = t & 63;
    for (int nl = (t >> 6); nl < 8; nl += 2) {
        int base = nl*16;
        float av[Kc];
        float mx = -3.4e38f;
        #pragma unroll
        for (int k = 0; k < Kc; k++) {
            av[k] = sOut[(base + k)*65 + d];
            mx = fmaxf(mx, av[k]);
        }
        float sum = 0.f;
        #pragma unroll
        for (int k = 0; k < Kc; k++) { av[k] = __expf(av[k] - mx); sum += av[k]; }
        float inv = 1.f / sum;
        const int* ip = g_idx + p0 + base;
        float agg = 0.f;
        #pragma unroll
        for (int k = 0; k < Kc; k++) {
            int iv = ip[k];
            float vg = g_v[((size_t)b*Mc + iv)*Dc + d];
            float pe = g_pe[(size_t)(p0 + base + k)*Dc + d];
            agg = fmaf(av[k]*inv, vg + pe, agg);
        }
        int bn = (p0 >> 4) + nl;
        g_agg[(size_t)bn*Dc + d] = agg;
    }
}

// ---------------- out = We @ agg + be + fq ---------------------------------
__global__ __launch_bounds__(512, 2)
void final_kernel(const float* __restrict__ be,
                  const float* __restrict__ fq, float* __restrict__ out) {
    extern __shared__ float sm8[];
    float* sWet = sm8;             // [64 d][128 c]
    float* sG  = sWet + Dc*Cc;     // [64 d][128 n]
    float* sbe = sG + Dc*128;      // 128
    int t = threadIdx.x;
    int b = blockIdx.y;
    int nblk = blockIdx.x * 128;
    for (int i = t; i < Cc*Dc/4; i += 512) ((float4*)sWet)[i] = ((const float4*)g_Wet)[i];
    if (t < Cc) sbe[t] = be[t];
    for (int f = t; f < 2048; f += 512) {
        int d4 = f >> 7, nl = f & 127;
        float4 v = *(const float4*)&g_agg[((size_t)b*Nc + nblk + nl)*Dc + d4*4];
        int d = d4*4;
        sG[(d+0)*128 + nl] = v.x;
        sG[(d+1)*128 + nl] = v.y;
        sG[(d+2)*128 + nl] = v.z;
        sG[(d+3)*128 + nl] = v.w;
    }
    __syncthreads();
    int og = t >> 4, pg = t & 15;
    int c0 = og*4, n0 = pg*8;
    u64 acc[4][4];
    #pragma unroll
    for (int q = 0; q < 4; q++)
        #pragma unroll
        for (int j = 0; j < 4; j++) acc[q][j] = 0ull;
    #pragma unroll 2
    for (int e = 0; e < Dc; e++) {
        ulonglong2 xa = *(const ulonglong2*)&sG[e*128 + n0];
        ulonglong2 xb = *(const ulonglong2*)&sG[e*128 + n0 + 4];
        float4 w4 = *(const float4*)&sWet[e*Cc + c0];
        float wf[4] = {w4.x, w4.y, w4.z, w4.w};
        #pragma unroll
        for (int q = 0; q < 4; q++) {
            u64 wp = pack2(wf[q], wf[q]);
            acc[q][0] = fma2(wp, xa.x, acc[q][0]);
            acc[q][1] = fma2(wp, xa.y, acc[q][1]);
            acc[q][2] = fma2(wp, xb.x, acc[q][2]);
            acc[q][3] = fma2(wp, xb.y, acc[q][3]);
        }
    }
    #pragma unroll
    for (int q = 0; q < 4; q++) {
        int c = c0 + q;
        float bc = sbe[c];
        float vv[8];
        #pragma unroll
        for (int j = 0; j < 4; j++) {
            float2 u = unpack2(acc[q][j]);
            vv[j*2+0] = u.x; vv[j*2+1] = u.y;
        }
        size_t o = (size_t)b*Cc*Nc + (size_t)c*Nc + nblk + n0;
        float4 f0 = *(const float4*)&fq[o];
        float4 f1 = *(const float4*)&fq[o + 4];
        *(float4*)&out[o]     = make_float4(vv[0]+bc+f0.x, vv[1]+bc+f0.y,
                                            vv[2]+bc+f0.z, vv[3]+bc+f0.w);
        *(float4*)&out[o + 4] = make_float4(vv[4]+bc+f1.x, vv[5]+bc+f1.y,
                                            vv[6]+bc+f1.z, vv[7]+bc+f1.w);
    }
}

// ---------------- launch -----------------------------------------------------
extern "C" void kernel_launch(void* const* d_in, const int* in_sizes, int n_in,
                              void* d_out, int out_size) {
    const float* pq  = (const float*)d_in[0];
    const float* fq  = (const float*)d_in[1];
    const float* ps  = (const float*)d_in[2];
    const float* fs  = (const float*)d_in[3];
    const float* Wq  = (const float*)d_in[4];  const float* bq  = (const float*)d_in[5];
    const float* Wk  = (const float*)d_in[6];  const float* bk  = (const float*)d_in[7];
    const float* Wv  = (const float*)d_in[8];  const float* bv  = (const float*)d_in[9];
    const float* Wp1 = (const float*)d_in[10]; const float* bp1 = (const float*)d_in[11];
    const float* gp  = (const float*)d_in[12]; const float* btp = (const float*)d_in[13];
    const float* Wp2 = (const float*)d_in[14]; const float* bp2 = (const float*)d_in[15];
    const float* Wa1 = (const float*)d_in[16]; const float* ba1 = (const float*)d_in[17];
    const float* ga  = (const float*)d_in[18]; const float* bta = (const float*)d_in[19];
    const float* Wa2 = (const float*)d_in[20]; const float* ba2 = (const float*)d_in[21];
    const float* We  = (const float*)d_in[22]; const float* be  = (const float*)d_in[23];
    float* out = (float*)d_out;

    const int SMEM_QKV = (Cc*Dc + 32*128 + Dc) * (int)sizeof(float);
    const int SMEM_KNN = 2048*16 + 64*65*4*2;
    const int SMEM_PA  = (16384 + Dc*128 + 3*Dc + Hc) * (int)sizeof(float);
    const int SMEM_A2  = (64*Dc + 8320 + 2*Hc + Dc) * (int)sizeof(float);
    const int SMEM_FIN = (Dc*Cc + Dc*128 + Cc) * (int)sizeof(float);
    cudaFuncSetAttribute(qkv_kernel,        cudaFuncAttributeMaxDynamicSharedMemorySize, SMEM_QKV);
    cudaFuncSetAttribute(knn_kernel,        cudaFuncAttributeMaxDynamicSharedMemorySize, SMEM_KNN);
    cudaFuncSetAttribute(pe2_a1_kernel,     cudaFuncAttributeMaxDynamicSharedMemorySize, SMEM_PA);
    cudaFuncSetAttribute(a2_softagg_kernel, cudaFuncAttributeMaxDynamicSharedMemorySize, SMEM_A2);
    cudaFuncSetAttribute(final_kernel,      cudaFuncAttributeMaxDynamicSharedMemorySize, SMEM_FIN);

    prep_kernel<<<dim3(16, 7), 256>>>(Wq, Wk, Wv, Wp2, Wa1, Wa2, We);
    qkv_kernel<<<dim3(Nc/128, 12), 512, SMEM_QKV>>>(fq, fs, bq, bk, bv);
    knn_kernel<<<dim3(Nc/64, Bc), 256, SMEM_KNN>>>(pq, ps);
    pe1_stats_kernel<<<NPTS/256, 256>>>(pq, ps, Wp1, bp1);
    pe2_a1_kernel<<<NPTS/128, 512, SMEM_PA>>>(bp2, gp, btp, ba1);
    a2_softagg_kernel<<<NPTS/128, 128, SMEM_A2>>>(ba2, ga, bta);
    final_kernel<<<dim3(Nc/128, Bc), 512, SMEM_FIN>>>(be, fq, out);
}